// round 1
// baseline (speedup 1.0000x reference)
#include <cuda_runtime.h>
#include <cuda_bf16.h>
#include <math.h>

// Problem constants
#define BATCH 4
#define SEQ   2048
#define QDIM  1024
#define HEADS 16
#define DHEAD 64
#define MROWS (BATCH*SEQ)          // 8192
#define SCALE 0.125f               // 64^-0.5

// Scratch (device globals: no allocations allowed)
__device__ float g_q[BATCH*HEADS*SEQ*DHEAD];     // [B,H,T,dh]
__device__ float g_k[BATCH*HEADS*SEQ*DHEAD];
__device__ float g_v[BATCH*HEADS*SEQ*DHEAD];
__device__ float g_att[MROWS*QDIM];              // [B,T,H*dh]

// ---------------------------------------------------------------------------
// GEMM tiles: BM=128, BN=64, BK=16, 256 threads, 8x4 per-thread microtile
// ---------------------------------------------------------------------------
#define BM 128
#define BN 64
#define BK 16

// Fused QKV projection: C = hidden @ W{q,k,v}, epilogue remaps to [B,H,T,dh]
__global__ __launch_bounds__(256) void qkv_gemm_kernel(
    const float* __restrict__ A,
    const float* __restrict__ Wq,
    const float* __restrict__ Wk,
    const float* __restrict__ Wv)
{
    const float* W = (blockIdx.z == 0) ? Wq : ((blockIdx.z == 1) ? Wk : Wv);
    float* dst     = (blockIdx.z == 0) ? g_q : ((blockIdx.z == 1) ? g_k : g_v);

    __shared__ float As[BK][BM + 4];
    __shared__ float Bs[BK][BN + 4];

    const int tid = threadIdx.x;
    const int tx = tid & 15;        // 0..15 -> 4 output cols
    const int ty = tid >> 4;        // 0..15 -> 8 output rows
    const int bm = blockIdx.x * BM;
    const int bn = blockIdx.y * BN; // == head * 64
    const int K = QDIM, N = QDIM;

    float acc[8][4];
    #pragma unroll
    for (int i = 0; i < 8; i++)
        #pragma unroll
        for (int j = 0; j < 4; j++) acc[i][j] = 0.f;

    for (int k0 = 0; k0 < K; k0 += BK) {
        // A tile: 128x16 floats = 512 float4, 2 per thread, store transposed
        #pragma unroll
        for (int l = 0; l < 2; l++) {
            int lin = tid + l * 256;
            int m = lin >> 2;
            int kg = lin & 3;
            float4 v = *reinterpret_cast<const float4*>(&A[(size_t)(bm + m) * K + k0 + kg * 4]);
            As[kg*4+0][m] = v.x; As[kg*4+1][m] = v.y;
            As[kg*4+2][m] = v.z; As[kg*4+3][m] = v.w;
        }
        // B tile: 16x64 floats = 256 float4, 1 per thread
        {
            int kr = tid >> 4;
            int ng = tid & 15;
            float4 v = *reinterpret_cast<const float4*>(&W[(size_t)(k0 + kr) * N + bn + ng * 4]);
            *reinterpret_cast<float4*>(&Bs[kr][ng * 4]) = v;
        }
        __syncthreads();

        #pragma unroll
        for (int k = 0; k < BK; k++) {
            float4 a0 = *reinterpret_cast<const float4*>(&As[k][ty * 8]);
            float4 a1 = *reinterpret_cast<const float4*>(&As[k][ty * 8 + 4]);
            float4 b  = *reinterpret_cast<const float4*>(&Bs[k][tx * 4]);
            float av[8] = {a0.x,a0.y,a0.z,a0.w,a1.x,a1.y,a1.z,a1.w};
            float bv[4] = {b.x,b.y,b.z,b.w};
            #pragma unroll
            for (int i = 0; i < 8; i++)
                #pragma unroll
                for (int j = 0; j < 4; j++) acc[i][j] += av[i] * bv[j];
        }
        __syncthreads();
    }

    // epilogue: remap (b,t, h*64+d) -> [B,H,T,dh]
    const int h = bn >> 6;
    #pragma unroll
    for (int i = 0; i < 8; i++) {
        int m = bm + ty * 8 + i;
        int b = m >> 11;           // / 2048
        int t = m & 2047;
        float4 v = make_float4(acc[i][0], acc[i][1], acc[i][2], acc[i][3]);
        *reinterpret_cast<float4*>(
            &dst[(((size_t)(b * HEADS + h) * SEQ + t) * DHEAD) + tx * 4]) = v;
    }
}

// Output projection: d_out = g_att @ Wo + bo
__global__ __launch_bounds__(256) void proj_gemm_kernel(
    const float* __restrict__ Wo,
    const float* __restrict__ bo,
    float* __restrict__ C)
{
    const float* A = g_att;
    __shared__ float As[BK][BM + 4];
    __shared__ float Bs[BK][BN + 4];

    const int tid = threadIdx.x;
    const int tx = tid & 15;
    const int ty = tid >> 4;
    const int bm = blockIdx.x * BM;
    const int bn = blockIdx.y * BN;
    const int K = QDIM, N = QDIM;

    float acc[8][4];
    #pragma unroll
    for (int i = 0; i < 8; i++)
        #pragma unroll
        for (int j = 0; j < 4; j++) acc[i][j] = 0.f;

    for (int k0 = 0; k0 < K; k0 += BK) {
        #pragma unroll
        for (int l = 0; l < 2; l++) {
            int lin = tid + l * 256;
            int m = lin >> 2;
            int kg = lin & 3;
            float4 v = *reinterpret_cast<const float4*>(&A[(size_t)(bm + m) * K + k0 + kg * 4]);
            As[kg*4+0][m] = v.x; As[kg*4+1][m] = v.y;
            As[kg*4+2][m] = v.z; As[kg*4+3][m] = v.w;
        }
        {
            int kr = tid >> 4;
            int ng = tid & 15;
            float4 v = *reinterpret_cast<const float4*>(&Wo[(size_t)(k0 + kr) * N + bn + ng * 4]);
            *reinterpret_cast<float4*>(&Bs[kr][ng * 4]) = v;
        }
        __syncthreads();

        #pragma unroll
        for (int k = 0; k < BK; k++) {
            float4 a0 = *reinterpret_cast<const float4*>(&As[k][ty * 8]);
            float4 a1 = *reinterpret_cast<const float4*>(&As[k][ty * 8 + 4]);
            float4 b  = *reinterpret_cast<const float4*>(&Bs[k][tx * 4]);
            float av[8] = {a0.x,a0.y,a0.z,a0.w,a1.x,a1.y,a1.z,a1.w};
            float bv[4] = {b.x,b.y,b.z,b.w};
            #pragma unroll
            for (int i = 0; i < 8; i++)
                #pragma unroll
                for (int j = 0; j < 4; j++) acc[i][j] += av[i] * bv[j];
        }
        __syncthreads();
    }

    float4 bias = *reinterpret_cast<const float4*>(&bo[bn + tx * 4]);
    #pragma unroll
    for (int i = 0; i < 8; i++) {
        int m = bm + ty * 8 + i;
        float4 v = make_float4(acc[i][0] + bias.x, acc[i][1] + bias.y,
                               acc[i][2] + bias.z, acc[i][3] + bias.w);
        *reinterpret_cast<float4*>(&C[(size_t)m * N + bn + tx * 4]) = v;
    }
}

// ---------------------------------------------------------------------------
// Flash attention: one CTA per (b, h, 64-row query block), 256 threads.
// Q^T, K^T in smem (conflict-free GEMM reads), V row-major, P staged in smem.
// ---------------------------------------------------------------------------
#define AP 68   // padded row stride (keeps float4 alignment, avoids conflicts)

__global__ __launch_bounds__(256) void attn_kernel(const int* __restrict__ mask)
{
    extern __shared__ float sm[];
    float (*QsT)[AP] = (float(*)[AP])(sm);                 // [64][68]  Q^T: [d][r]
    float (*KsT)[AP] = (float(*)[AP])(sm + 64 * AP);       // [64][68]  K^T: [d][c]
    float (*Vs )[AP] = (float(*)[AP])(sm + 2 * 64 * AP);   // [64][68]  V:   [j][d]
    float (*Ps )[AP] = (float(*)[AP])(sm + 3 * 64 * AP);   // [64][68]  P:   [r][j]
    int* msk = (int*)(sm + 4 * 64 * AP);                   // [64]

    const int tid = threadIdx.x;
    const int tx = tid & 15;       // 4 cols / dims
    const int ty = tid >> 4;       // 4 rows
    const int qb = blockIdx.x;     // query block (0..31)
    const int h  = blockIdx.y;
    const int b  = blockIdx.z;

    const float* qptr = &g_q[((size_t)(b * HEADS + h) * SEQ + qb * 64) * DHEAD];

    // Load Q block transposed, pre-scaled
    #pragma unroll
    for (int l = 0; l < 4; l++) {
        int lin = tid + l * 256;       // 0..1023 float4 units
        int r  = lin >> 4;             // row 0..63
        int dg = lin & 15;             // d group
        float4 v = *reinterpret_cast<const float4*>(&qptr[r * DHEAD + dg * 4]);
        QsT[dg*4+0][r] = v.x * SCALE; QsT[dg*4+1][r] = v.y * SCALE;
        QsT[dg*4+2][r] = v.z * SCALE; QsT[dg*4+3][r] = v.w * SCALE;
    }
    __syncthreads();

    float m_i[4], l_i[4], acc[4][4];
    #pragma unroll
    for (int i = 0; i < 4; i++) {
        m_i[i] = -1e30f; l_i[i] = 0.f;
        #pragma unroll
        for (int j = 0; j < 4; j++) acc[i][j] = 0.f;
    }

    for (int kb = 0; kb < SEQ / 64; kb++) {
        const float* kptr = &g_k[((size_t)(b * HEADS + h) * SEQ + kb * 64) * DHEAD];
        const float* vptr = &g_v[((size_t)(b * HEADS + h) * SEQ + kb * 64) * DHEAD];

        // Load K^T and V
        #pragma unroll
        for (int l = 0; l < 4; l++) {
            int lin = tid + l * 256;
            int r  = lin >> 4;
            int dg = lin & 15;
            float4 kv = *reinterpret_cast<const float4*>(&kptr[r * DHEAD + dg * 4]);
            KsT[dg*4+0][r] = kv.x; KsT[dg*4+1][r] = kv.y;
            KsT[dg*4+2][r] = kv.z; KsT[dg*4+3][r] = kv.w;
            float4 vv = *reinterpret_cast<const float4*>(&vptr[r * DHEAD + dg * 4]);
            *reinterpret_cast<float4*>(&Vs[r][dg * 4]) = vv;
        }
        if (tid < 64) msk[tid] = mask[b * SEQ + kb * 64 + tid];
        __syncthreads();

        // S = Q K^T  (rows ty*4+i, cols tx*4+j)
        float s[4][4];
        #pragma unroll
        for (int i = 0; i < 4; i++)
            #pragma unroll
            for (int j = 0; j < 4; j++) s[i][j] = 0.f;

        #pragma unroll 4
        for (int d = 0; d < DHEAD; d++) {
            float4 a = *reinterpret_cast<const float4*>(&QsT[d][ty * 4]);
            float4 c = *reinterpret_cast<const float4*>(&KsT[d][tx * 4]);
            float av[4] = {a.x,a.y,a.z,a.w};
            float cv[4] = {c.x,c.y,c.z,c.w};
            #pragma unroll
            for (int i = 0; i < 4; i++)
                #pragma unroll
                for (int j = 0; j < 4; j++) s[i][j] += av[i] * cv[j];
        }

        // key mask
        float mb[4];
        #pragma unroll
        for (int j = 0; j < 4; j++)
            mb[j] = (msk[tx * 4 + j] == 0) ? -1e30f : 0.0f;
        #pragma unroll
        for (int i = 0; i < 4; i++)
            #pragma unroll
            for (int j = 0; j < 4; j++) s[i][j] += mb[j];

        // online softmax per row (reduce across the 16 tx lanes, width-16 shuffles)
        #pragma unroll
        for (int i = 0; i < 4; i++) {
            float rmax = fmaxf(fmaxf(s[i][0], s[i][1]), fmaxf(s[i][2], s[i][3]));
            #pragma unroll
            for (int off = 8; off >= 1; off >>= 1)
                rmax = fmaxf(rmax, __shfl_xor_sync(0xffffffffu, rmax, off, 16));
            float mnew = fmaxf(m_i[i], rmax);
            float p[4], rsum = 0.f;
            #pragma unroll
            for (int j = 0; j < 4; j++) { p[j] = __expf(s[i][j] - mnew); rsum += p[j]; }
            #pragma unroll
            for (int off = 8; off >= 1; off >>= 1)
                rsum += __shfl_xor_sync(0xffffffffu, rsum, off, 16);
            float alpha = __expf(m_i[i] - mnew);
            l_i[i] = l_i[i] * alpha + rsum;
            m_i[i] = mnew;
            #pragma unroll
            for (int j = 0; j < 4; j++) acc[i][j] *= alpha;
            #pragma unroll
            for (int j = 0; j < 4; j++) Ps[ty * 4 + i][tx * 4 + j] = p[j];
        }
        __syncthreads();

        // O += P @ V  (dims tx*4+j)
        #pragma unroll 4
        for (int jj = 0; jj < 64; jj++) {
            float4 vv = *reinterpret_cast<const float4*>(&Vs[jj][tx * 4]);
            float vvv[4] = {vv.x,vv.y,vv.z,vv.w};
            #pragma unroll
            for (int i = 0; i < 4; i++) {
                float p = Ps[ty * 4 + i][jj];
                #pragma unroll
                for (int j = 0; j < 4; j++) acc[i][j] += p * vvv[j];
            }
        }
        __syncthreads();
    }

    // epilogue: write [B, T, H*dh]
    #pragma unroll
    for (int i = 0; i < 4; i++) {
        float inv = 1.0f / l_i[i];
        int t = qb * 64 + ty * 4 + i;
        float4 v = make_float4(acc[i][0] * inv, acc[i][1] * inv,
                               acc[i][2] * inv, acc[i][3] * inv);
        *reinterpret_cast<float4*>(
            &g_att[((size_t)(b * SEQ + t) * QDIM) + h * DHEAD + tx * 4]) = v;
    }
}

// ---------------------------------------------------------------------------
extern "C" void kernel_launch(void* const* d_in, const int* in_sizes, int n_in,
                              void* d_out, int out_size)
{
    const float* hidden = (const float*)d_in[0];
    const int*   amask  = (const int*)d_in[1];
    const float* Wq     = (const float*)d_in[2];
    const float* Wk     = (const float*)d_in[3];
    const float* Wv     = (const float*)d_in[4];
    const float* Wo     = (const float*)d_in[5];
    const float* bo     = (const float*)d_in[6];
    float* out          = (float*)d_out;

    const int smem_attn = (4 * 64 * AP) * (int)sizeof(float) + 64 * (int)sizeof(int);
    cudaFuncSetAttribute(attn_kernel, cudaFuncAttributeMaxDynamicSharedMemorySize, smem_attn);

    dim3 gq(MROWS / BM, QDIM / BN, 3);
    qkv_gemm_kernel<<<gq, 256>>>(hidden, Wq, Wk, Wv);

    dim3 ga(SEQ / 64, HEADS, BATCH);
    attn_kernel<<<ga, 256, smem_attn>>>(amask);

    dim3 gp(MROWS / BM, QDIM / BN);
    proj_gemm_kernel<<<gp, 256>>>(Wo, bo, out);
}

// round 2
// speedup vs baseline: 2.2593x; 2.2593x over previous
#include <cuda_runtime.h>
#include <math.h>

// Problem constants
#define BATCH 4
#define SEQ   2048
#define QDIM  1024
#define HEADS 16
#define DHEAD 64
#define MROWS (BATCH*SEQ)          // 8192
#define SCALE 0.125f               // 64^-0.5

// Scratch (device globals: no allocations allowed)
__device__ float g_q[BATCH*HEADS*SEQ*DHEAD];     // [B,H,T,dh]
__device__ float g_k[BATCH*HEADS*SEQ*DHEAD];
__device__ float g_v[BATCH*HEADS*SEQ*DHEAD];
__device__ float g_att[MROWS*QDIM];              // [B,T,H*dh]

// ---------------------------------------------------------------------------
// tf32 helpers
// ---------------------------------------------------------------------------
__device__ __forceinline__ unsigned f2tf(float x) {
    unsigned r;
    asm("cvt.rna.tf32.f32 %0, %1;" : "=r"(r) : "f"(x));
    return r;
}
__device__ __forceinline__ uint4 tf4(float4 v) {
    return make_uint4(f2tf(v.x), f2tf(v.y), f2tf(v.z), f2tf(v.w));
}
// D += A(16x8) * B(8x8), tf32 inputs, f32 accum
__device__ __forceinline__ void mma8(float c[4], const unsigned a[4], const unsigned b[2]) {
    asm volatile(
        "mma.sync.aligned.m16n8k8.row.col.f32.tf32.tf32.f32 "
        "{%0,%1,%2,%3}, {%4,%5,%6,%7}, {%8,%9}, {%0,%1,%2,%3};"
        : "+f"(c[0]), "+f"(c[1]), "+f"(c[2]), "+f"(c[3])
        : "r"(a[0]), "r"(a[1]), "r"(a[2]), "r"(a[3]), "r"(b[0]), "r"(b[1]));
}

// ---------------------------------------------------------------------------
// Dense GEMM tiles: BM=128, BN=64, BK=32, 256 threads = 8 warps (4m x 2n),
// warp tile 32x32 (mma grid 2m x 4n). Conflict-free padded smem.
// ---------------------------------------------------------------------------
#define GBM 128
#define GBN 64
#define GBK 32
#define ASTR 36   // GBK+4: A frag banks (4r + k) all distinct
#define BSTR 72   // GBN+8: B frag banks (8k + n) all distinct

__device__ __forceinline__ void gemm_tile_compute(
    const unsigned (*As)[ASTR], const unsigned (*Bs)[BSTR],
    int wm, int wn, int lane, float acc[2][4][4])
{
    const int r = lane >> 2, kq = lane & 3;
    #pragma unroll
    for (int kk = 0; kk < GBK; kk += 8) {
        unsigned af[2][4], bf[4][2];
        #pragma unroll
        for (int mi = 0; mi < 2; mi++) {
            int mr = wm * 32 + mi * 16 + r;
            af[mi][0] = As[mr][kk + kq];
            af[mi][1] = As[mr + 8][kk + kq];
            af[mi][2] = As[mr][kk + kq + 4];
            af[mi][3] = As[mr + 8][kk + kq + 4];
        }
        #pragma unroll
        for (int ni = 0; ni < 4; ni++) {
            int nc = wn * 32 + ni * 8 + r;
            bf[ni][0] = Bs[kk + kq][nc];
            bf[ni][1] = Bs[kk + kq + 4][nc];
        }
        #pragma unroll
        for (int mi = 0; mi < 2; mi++)
            #pragma unroll
            for (int ni = 0; ni < 4; ni++)
                mma8(acc[mi][ni], af[mi], bf[ni]);
    }
}

// Fused QKV projection, epilogue remaps to [B,H,T,dh]
__global__ __launch_bounds__(256) void qkv_tf32_kernel(
    const float* __restrict__ A,
    const float* __restrict__ Wq,
    const float* __restrict__ Wk,
    const float* __restrict__ Wv)
{
    const float* W = (blockIdx.z == 0) ? Wq : ((blockIdx.z == 1) ? Wk : Wv);
    float* dst     = (blockIdx.z == 0) ? g_q : ((blockIdx.z == 1) ? g_k : g_v);

    __shared__ unsigned As[GBM][ASTR];
    __shared__ unsigned Bs[GBK][BSTR];

    const int tid = threadIdx.x, lane = tid & 31, warp = tid >> 5;
    const int wm = warp & 3, wn = warp >> 2;
    const int bm = blockIdx.x * GBM;
    const int bn = blockIdx.y * GBN;

    float acc[2][4][4];
    #pragma unroll
    for (int mi = 0; mi < 2; mi++)
        #pragma unroll
        for (int ni = 0; ni < 4; ni++)
            #pragma unroll
            for (int c = 0; c < 4; c++) acc[mi][ni][c] = 0.f;

    for (int k0 = 0; k0 < QDIM; k0 += GBK) {
        #pragma unroll
        for (int l = 0; l < 4; l++) {
            int lin = tid + l * 256;          // 0..1023 float4 units
            int row = lin >> 3, kg = lin & 7;
            float4 v = *reinterpret_cast<const float4*>(
                &A[(size_t)(bm + row) * QDIM + k0 + kg * 4]);
            *reinterpret_cast<uint4*>(&As[row][kg * 4]) = tf4(v);
        }
        #pragma unroll
        for (int l = 0; l < 2; l++) {
            int lin = tid + l * 256;          // 0..511 float4 units
            int row = lin >> 4, ng = lin & 15;
            float4 v = *reinterpret_cast<const float4*>(
                &W[(size_t)(k0 + row) * QDIM + bn + ng * 4]);
            *reinterpret_cast<uint4*>(&Bs[row][ng * 4]) = tf4(v);
        }
        __syncthreads();
        gemm_tile_compute(As, Bs, wm, wn, lane, acc);
        __syncthreads();
    }

    // epilogue: block spans exactly one head (GBN == DHEAD)
    const int r = lane >> 2, kq = lane & 3;
    const int h = blockIdx.y;
    #pragma unroll
    for (int mi = 0; mi < 2; mi++) {
        #pragma unroll
        for (int ni = 0; ni < 4; ni++) {
            int m0 = bm + wm * 32 + mi * 16 + r;
            int d  = wn * 32 + ni * 8 + 2 * kq;
            int b0 = m0 >> 11, t0 = m0 & 2047;
            *reinterpret_cast<float2*>(
                &dst[(((size_t)(b0 * HEADS + h) * SEQ + t0) * DHEAD) + d]) =
                make_float2(acc[mi][ni][0], acc[mi][ni][1]);
            int m1 = m0 + 8;
            int b1 = m1 >> 11, t1 = m1 & 2047;
            *reinterpret_cast<float2*>(
                &dst[(((size_t)(b1 * HEADS + h) * SEQ + t1) * DHEAD) + d]) =
                make_float2(acc[mi][ni][2], acc[mi][ni][3]);
        }
    }
}

// Output projection: d_out = g_att @ Wo + bo
__global__ __launch_bounds__(256) void proj_tf32_kernel(
    const float* __restrict__ Wo,
    const float* __restrict__ bo,
    float* __restrict__ C)
{
    const float* A = g_att;
    __shared__ unsigned As[GBM][ASTR];
    __shared__ unsigned Bs[GBK][BSTR];

    const int tid = threadIdx.x, lane = tid & 31, warp = tid >> 5;
    const int wm = warp & 3, wn = warp >> 2;
    const int bm = blockIdx.x * GBM;
    const int bn = blockIdx.y * GBN;

    float acc[2][4][4];
    #pragma unroll
    for (int mi = 0; mi < 2; mi++)
        #pragma unroll
        for (int ni = 0; ni < 4; ni++)
            #pragma unroll
            for (int c = 0; c < 4; c++) acc[mi][ni][c] = 0.f;

    for (int k0 = 0; k0 < QDIM; k0 += GBK) {
        #pragma unroll
        for (int l = 0; l < 4; l++) {
            int lin = tid + l * 256;
            int row = lin >> 3, kg = lin & 7;
            float4 v = *reinterpret_cast<const float4*>(
                &A[(size_t)(bm + row) * QDIM + k0 + kg * 4]);
            *reinterpret_cast<uint4*>(&As[row][kg * 4]) = tf4(v);
        }
        #pragma unroll
        for (int l = 0; l < 2; l++) {
            int lin = tid + l * 256;
            int row = lin >> 4, ng = lin & 15;
            float4 v = *reinterpret_cast<const float4*>(
                &Wo[(size_t)(k0 + row) * QDIM + bn + ng * 4]);
            *reinterpret_cast<uint4*>(&Bs[row][ng * 4]) = tf4(v);
        }
        __syncthreads();
        gemm_tile_compute(As, Bs, wm, wn, lane, acc);
        __syncthreads();
    }

    const int r = lane >> 2, kq = lane & 3;
    #pragma unroll
    for (int mi = 0; mi < 2; mi++) {
        #pragma unroll
        for (int ni = 0; ni < 4; ni++) {
            int m0 = bm + wm * 32 + mi * 16 + r;
            int d  = wn * 32 + ni * 8 + 2 * kq;
            float b0v = bo[bn + d], b1v = bo[bn + d + 1];
            *reinterpret_cast<float2*>(&C[(size_t)m0 * QDIM + bn + d]) =
                make_float2(acc[mi][ni][0] + b0v, acc[mi][ni][1] + b1v);
            *reinterpret_cast<float2*>(&C[(size_t)(m0 + 8) * QDIM + bn + d]) =
                make_float2(acc[mi][ni][2] + b0v, acc[mi][ni][3] + b1v);
        }
    }
}

// ---------------------------------------------------------------------------
// Flash attention with tf32 MMA: one CTA per (b, h, 64-query block),
// 256 threads = 8 warps (4m x 2n), warp tile 16x32 for both S and PV MMAs.
// S staged in smem for the masked online softmax.
// ---------------------------------------------------------------------------
#define QS 68   // stride for Qs/Ks/Ps: frag banks (4*row + k) distinct
#define VSS 72  // stride for Vs: frag banks (8*k + n) distinct

__global__ __launch_bounds__(256) void attn_tf32_kernel(const int* __restrict__ mask)
{
    extern __shared__ unsigned smu[];
    unsigned (*Qs)[QS]  = (unsigned(*)[QS])smu;                       // [64][68] tf32 Q (m,k)
    unsigned (*Ks)[QS]  = (unsigned(*)[QS])(smu + 64 * QS);           // [64][68] tf32 K (n,k)
    unsigned (*Vs)[VSS] = (unsigned(*)[VSS])(smu + 2 * 64 * QS);      // [64][72] tf32 V (k=j, n=d)
    float (*Ps)[QS]     = (float(*)[QS])(smu + 2 * 64 * QS + 64 * VSS); // [64][68] S scores then P
    float* alphas       = (float*)(smu + 3 * 64 * QS + 64 * VSS);     // [64]
    int*   msk          = (int*)(alphas + 64);                        // [64]

    const int tid = threadIdx.x, lane = tid & 31, warp = tid >> 5;
    const int wm = warp & 3, wn = warp >> 2;
    const int r = lane >> 2, kq = lane & 3;
    const int qb = blockIdx.x, h = blockIdx.y, b = blockIdx.z;

    const float* qptr = &g_q[((size_t)(b * HEADS + h) * SEQ + qb * 64) * DHEAD];

    // Load Q (pre-scaled, tf32)
    #pragma unroll
    for (int l = 0; l < 4; l++) {
        int lin = tid + l * 256;       // 0..1023 float4 units
        int rr = lin >> 4, dg = lin & 15;
        float4 v = *reinterpret_cast<const float4*>(&qptr[rr * DHEAD + dg * 4]);
        *reinterpret_cast<uint4*>(&Qs[rr][dg * 4]) =
            make_uint4(f2tf(v.x * SCALE), f2tf(v.y * SCALE),
                       f2tf(v.z * SCALE), f2tf(v.w * SCALE));
    }

    float oacc[4][4];
    #pragma unroll
    for (int ni = 0; ni < 4; ni++)
        #pragma unroll
        for (int c = 0; c < 4; c++) oacc[ni][c] = 0.f;

    // softmax row state: warp w owns rows w*8 .. w*8+7 (value replicated per lane)
    float mprev[8], lsum[8];
    #pragma unroll
    for (int rr = 0; rr < 8; rr++) { mprev[rr] = -1e30f; lsum[rr] = 0.f; }

    for (int kb = 0; kb < SEQ / 64; kb++) {
        __syncthreads();   // protect Ks/Vs/Ps/alphas from previous iteration readers
        const float* kp = &g_k[((size_t)(b * HEADS + h) * SEQ + kb * 64) * DHEAD];
        const float* vp = &g_v[((size_t)(b * HEADS + h) * SEQ + kb * 64) * DHEAD];
        #pragma unroll
        for (int l = 0; l < 4; l++) {
            int lin = tid + l * 256;
            int rr = lin >> 4, dg = lin & 15;
            float4 kv = *reinterpret_cast<const float4*>(&kp[rr * DHEAD + dg * 4]);
            *reinterpret_cast<uint4*>(&Ks[rr][dg * 4]) = tf4(kv);
            float4 vv = *reinterpret_cast<const float4*>(&vp[rr * DHEAD + dg * 4]);
            *reinterpret_cast<uint4*>(&Vs[rr][dg * 4]) = tf4(vv);
        }
        if (tid < 64) msk[tid] = mask[b * SEQ + kb * 64 + tid];
        __syncthreads();

        // ---- S = Q K^T (warp tile 16x32) ----
        float sacc[4][4];
        #pragma unroll
        for (int ni = 0; ni < 4; ni++)
            #pragma unroll
            for (int c = 0; c < 4; c++) sacc[ni][c] = 0.f;

        #pragma unroll
        for (int kk = 0; kk < DHEAD; kk += 8) {
            unsigned af[4];
            int mr = wm * 16 + r;
            af[0] = Qs[mr][kk + kq];
            af[1] = Qs[mr + 8][kk + kq];
            af[2] = Qs[mr][kk + kq + 4];
            af[3] = Qs[mr + 8][kk + kq + 4];
            #pragma unroll
            for (int ni = 0; ni < 4; ni++) {
                unsigned bf[2];
                int nc = wn * 32 + ni * 8 + r;
                bf[0] = Ks[nc][kk + kq];
                bf[1] = Ks[nc][kk + kq + 4];
                mma8(sacc[ni], af, bf);
            }
        }
        // stage S to smem
        #pragma unroll
        for (int ni = 0; ni < 4; ni++) {
            int mr = wm * 16 + r;
            int nc = wn * 32 + ni * 8 + 2 * kq;
            *reinterpret_cast<float2*>(&Ps[mr][nc])     = make_float2(sacc[ni][0], sacc[ni][1]);
            *reinterpret_cast<float2*>(&Ps[mr + 8][nc]) = make_float2(sacc[ni][2], sacc[ni][3]);
        }
        __syncthreads();

        // ---- masked online softmax: warp w -> rows w*8..w*8+7, 2 cols/lane ----
        float mb0 = (msk[lane]      == 0) ? -1e30f : 0.f;
        float mb1 = (msk[lane + 32] == 0) ? -1e30f : 0.f;
        #pragma unroll
        for (int rr = 0; rr < 8; rr++) {
            int row = warp * 8 + rr;
            float s0 = Ps[row][lane]      + mb0;
            float s1 = Ps[row][lane + 32] + mb1;
            float rmax = fmaxf(s0, s1);
            #pragma unroll
            for (int off = 16; off >= 1; off >>= 1)
                rmax = fmaxf(rmax, __shfl_xor_sync(0xffffffffu, rmax, off));
            float mnew = fmaxf(mprev[rr], rmax);
            float p0 = __expf(s0 - mnew), p1 = __expf(s1 - mnew);
            float rs = p0 + p1;
            #pragma unroll
            for (int off = 16; off >= 1; off >>= 1)
                rs += __shfl_xor_sync(0xffffffffu, rs, off);
            float al = __expf(mprev[rr] - mnew);
            lsum[rr] = lsum[rr] * al + rs;
            mprev[rr] = mnew;
            Ps[row][lane]      = p0;
            Ps[row][lane + 32] = p1;
            if (lane == 0) alphas[row] = al;
        }
        __syncthreads();

        // ---- rescale O, then O += P V ----
        float ala = alphas[wm * 16 + r];
        float alb = alphas[wm * 16 + r + 8];
        #pragma unroll
        for (int ni = 0; ni < 4; ni++) {
            oacc[ni][0] *= ala; oacc[ni][1] *= ala;
            oacc[ni][2] *= alb; oacc[ni][3] *= alb;
        }
        #pragma unroll
        for (int kk = 0; kk < 64; kk += 8) {
            unsigned af[4];
            int mr = wm * 16 + r;
            af[0] = f2tf(Ps[mr][kk + kq]);
            af[1] = f2tf(Ps[mr + 8][kk + kq]);
            af[2] = f2tf(Ps[mr][kk + kq + 4]);
            af[3] = f2tf(Ps[mr + 8][kk + kq + 4]);
            #pragma unroll
            for (int ni = 0; ni < 4; ni++) {
                unsigned bf[2];
                int nc = wn * 32 + ni * 8 + r;
                bf[0] = Vs[kk + kq][nc];
                bf[1] = Vs[kk + kq + 4][nc];
                mma8(oacc[ni], af, bf);
            }
        }
    }

    __syncthreads();
    // publish 1/l per row
    if (lane == 0) {
        #pragma unroll
        for (int rr = 0; rr < 8; rr++) alphas[warp * 8 + rr] = 1.f / lsum[rr];
    }
    __syncthreads();

    float inva = alphas[wm * 16 + r];
    float invb = alphas[wm * 16 + r + 8];
    #pragma unroll
    for (int ni = 0; ni < 4; ni++) {
        int m0 = wm * 16 + r;
        int d  = wn * 32 + ni * 8 + 2 * kq;
        int t0 = qb * 64 + m0;
        *reinterpret_cast<float2*>(
            &g_att[((size_t)(b * SEQ + t0) * QDIM) + h * DHEAD + d]) =
            make_float2(oacc[ni][0] * inva, oacc[ni][1] * inva);
        int t1 = t0 + 8;
        *reinterpret_cast<float2*>(
            &g_att[((size_t)(b * SEQ + t1) * QDIM) + h * DHEAD + d]) =
            make_float2(oacc[ni][2] * invb, oacc[ni][3] * invb);
    }
}

// ---------------------------------------------------------------------------
extern "C" void kernel_launch(void* const* d_in, const int* in_sizes, int n_in,
                              void* d_out, int out_size)
{
    const float* hidden = (const float*)d_in[0];
    const int*   amask  = (const int*)d_in[1];
    const float* Wq     = (const float*)d_in[2];
    const float* Wk     = (const float*)d_in[3];
    const float* Wv     = (const float*)d_in[4];
    const float* Wo     = (const float*)d_in[5];
    const float* bo     = (const float*)d_in[6];
    float* out          = (float*)d_out;

    const int smem_attn = (64 * (2 * QS + VSS + QS) + 64 + 64) * (int)sizeof(float);
    static int attr_set = 0;
    cudaFuncSetAttribute(attn_tf32_kernel, cudaFuncAttributeMaxDynamicSharedMemorySize, smem_attn);
    (void)attr_set;

    dim3 gq(MROWS / GBM, QDIM / GBN, 3);
    qkv_tf32_kernel<<<gq, 256>>>(hidden, Wq, Wk, Wv);

    dim3 ga(SEQ / 64, HEADS, BATCH);
    attn_tf32_kernel<<<ga, 256, smem_attn>>>(amask);

    dim3 gp(MROWS / GBM, QDIM / GBN);
    proj_tf32_kernel<<<gp, 256>>>(Wo, bo, out);
}

// round 4
// speedup vs baseline: 2.7835x; 1.2320x over previous
#include <cuda_runtime.h>
#include <math.h>

#define BATCH 4
#define SEQ   2048
#define QDIM  1024
#define HEADS 16
#define DHEAD 64
#define MROWS (BATCH*SEQ)          // 8192
#define SCALE 0.125f

// tf32 scratch (device globals: no allocations allowed)
__device__ unsigned hid_tf[MROWS*QDIM];
__device__ unsigned wq_tf[QDIM*QDIM];
__device__ unsigned wk_tf[QDIM*QDIM];
__device__ unsigned wv_tf[QDIM*QDIM];
__device__ unsigned wo_tf[QDIM*QDIM];
__device__ unsigned g_q[BATCH*HEADS*SEQ*DHEAD];   // [B,H,T,dh] tf32 (pre-scaled)
__device__ unsigned g_k[BATCH*HEADS*SEQ*DHEAD];
__device__ unsigned g_v[BATCH*HEADS*SEQ*DHEAD];
__device__ unsigned g_att[MROWS*QDIM];            // [B,T,H*dh] tf32

// ---------------------------------------------------------------------------
__device__ __forceinline__ unsigned f2tf(float x) {
    unsigned r;
    asm("cvt.rna.tf32.f32 %0, %1;" : "=r"(r) : "f"(x));
    return r;
}
__device__ __forceinline__ uint4 tf4(float4 v) {
    return make_uint4(f2tf(v.x), f2tf(v.y), f2tf(v.z), f2tf(v.w));
}
__device__ __forceinline__ void mma8(float c[4], const unsigned a[4], const unsigned b[2]) {
    asm volatile(
        "mma.sync.aligned.m16n8k8.row.col.f32.tf32.tf32.f32 "
        "{%0,%1,%2,%3}, {%4,%5,%6,%7}, {%8,%9}, {%0,%1,%2,%3};"
        : "+f"(c[0]), "+f"(c[1]), "+f"(c[2]), "+f"(c[3])
        : "r"(a[0]), "r"(a[1]), "r"(a[2]), "r"(a[3]), "r"(b[0]), "r"(b[1]));
}

// ---------------------------------------------------------------------------
// One-shot tf32 conversion (Wq pre-scaled by SCALE so q comes out scaled)
// ---------------------------------------------------------------------------
#define HID4 (MROWS*QDIM/4)
#define W4   (QDIM*QDIM/4)
__global__ __launch_bounds__(256) void cvt_kernel(
    const float* __restrict__ hidden,
    const float* __restrict__ Wq, const float* __restrict__ Wk,
    const float* __restrict__ Wv, const float* __restrict__ Wo)
{
    int i = blockIdx.x * blockDim.x + threadIdx.x;
    if (i < HID4) {
        float4 v = reinterpret_cast<const float4*>(hidden)[i];
        reinterpret_cast<uint4*>(hid_tf)[i] = tf4(v);
    } else {
        int rel = i - HID4;
        int w = rel / W4, off = rel - w * W4;
        const float* src = (w == 0) ? Wq : (w == 1) ? Wk : (w == 2) ? Wv : Wo;
        unsigned*   dst  = (w == 0) ? wq_tf : (w == 1) ? wk_tf : (w == 2) ? wv_tf : wo_tf;
        float4 v = reinterpret_cast<const float4*>(src)[off];
        if (w == 0) { v.x *= SCALE; v.y *= SCALE; v.z *= SCALE; v.w *= SCALE; }
        reinterpret_cast<uint4*>(dst)[off] = tf4(v);
    }
}

// ---------------------------------------------------------------------------
// Dense GEMM: CTA 128x128x32, 8 warps (2m x 4n), warp tile 64x32.
// A smem: interleaved-k [128][56]; B smem: [32][136].
// ---------------------------------------------------------------------------
#define GBM 128
#define GBN 128
#define GBK 32
#define AST 56
#define BST 136

__device__ __forceinline__ void load_tiles(
    unsigned* As, unsigned* Bs,
    const unsigned* __restrict__ A, const unsigned* __restrict__ B,
    int bm, int bn, int k0, int tid)
{
    #pragma unroll
    for (int l = 0; l < 4; l++) {
        int lin = tid + l * 256;
        int row = lin >> 3, kg = lin & 7;
        uint4 v = *reinterpret_cast<const uint4*>(&A[(size_t)(bm + row) * QDIM + k0 + kg * 4]);
        unsigned* d = &As[row * AST + (kg >> 1) * 8 + (kg & 1)];
        d[0] = v.x; d[2] = v.y; d[4] = v.z; d[6] = v.w;
    }
    #pragma unroll
    for (int l = 0; l < 4; l++) {
        int lin = tid + l * 256;
        int kk = lin >> 5, ng = lin & 31;
        uint4 v = *reinterpret_cast<const uint4*>(&B[(size_t)(k0 + kk) * QDIM + bn + ng * 4]);
        *reinterpret_cast<uint4*>(&Bs[kk * BST + ng * 4]) = v;
    }
}

__device__ __forceinline__ void gemm_tile(
    const unsigned* As, const unsigned* Bs,
    int wm, int wn, int r, int kq, float acc[4][4][4])
{
    #pragma unroll
    for (int s = 0; s < 4; s++) {
        unsigned af[4][4];
        #pragma unroll
        for (int mi = 0; mi < 4; mi++) {
            int row = wm * 64 + mi * 16 + r;
            uint2 lo = *reinterpret_cast<const uint2*>(&As[row * AST + s * 8 + 2 * kq]);
            uint2 hi = *reinterpret_cast<const uint2*>(&As[(row + 8) * AST + s * 8 + 2 * kq]);
            af[mi][0] = lo.x; af[mi][2] = lo.y; af[mi][1] = hi.x; af[mi][3] = hi.y;
        }
        #pragma unroll
        for (int ni = 0; ni < 4; ni++) {
            int c = wn * 32 + ni * 8 + r;
            unsigned bf[2];
            bf[0] = Bs[(s * 8 + kq) * BST + c];
            bf[1] = Bs[(s * 8 + kq + 4) * BST + c];
            #pragma unroll
            for (int mi = 0; mi < 4; mi++) mma8(acc[mi][ni], af[mi], bf);
        }
    }
}

// Fused QKV projection -> g_q/g_k/g_v tf32 [B,H,T,dh]
__global__ __launch_bounds__(256, 2) void qkv_kernel()
{
    const unsigned* B = (blockIdx.z == 0) ? wq_tf : ((blockIdx.z == 1) ? wk_tf : wv_tf);
    unsigned* dst     = (blockIdx.z == 0) ? g_q  : ((blockIdx.z == 1) ? g_k  : g_v);

    __shared__ unsigned As[GBM * AST];
    __shared__ unsigned Bs[GBK * BST];

    const int tid = threadIdx.x, lane = tid & 31, warp = tid >> 5;
    const int wm = warp >> 2, wn = warp & 3;
    const int r = lane >> 2, kq = lane & 3;
    const int bm = blockIdx.x * GBM;
    const int bn = blockIdx.y * GBN;

    float acc[4][4][4];
    #pragma unroll
    for (int mi = 0; mi < 4; mi++)
        #pragma unroll
        for (int ni = 0; ni < 4; ni++)
            #pragma unroll
            for (int c = 0; c < 4; c++) acc[mi][ni][c] = 0.f;

    for (int k0 = 0; k0 < QDIM; k0 += GBK) {
        load_tiles(As, Bs, hid_tf, B, bm, bn, k0, tid);
        __syncthreads();
        gemm_tile(As, Bs, wm, wn, r, kq, acc);
        __syncthreads();
    }

    #pragma unroll
    for (int mi = 0; mi < 4; mi++) {
        #pragma unroll
        for (int ni = 0; ni < 4; ni++) {
            int m0 = bm + wm * 64 + mi * 16 + r;
            int d  = wn * 32 + ni * 8 + 2 * kq;
            int head = blockIdx.y * 2 + (d >> 6);
            int dd = d & 63;
            int b0 = m0 >> 11, t0 = m0 & 2047;
            *reinterpret_cast<uint2*>(
                &dst[(((size_t)(b0 * HEADS + head) * SEQ + t0) * DHEAD) + dd]) =
                make_uint2(f2tf(acc[mi][ni][0]), f2tf(acc[mi][ni][1]));
            int m1 = m0 + 8;
            int b1 = m1 >> 11, t1 = m1 & 2047;
            *reinterpret_cast<uint2*>(
                &dst[(((size_t)(b1 * HEADS + head) * SEQ + t1) * DHEAD) + dd]) =
                make_uint2(f2tf(acc[mi][ni][2]), f2tf(acc[mi][ni][3]));
        }
    }
}

// Output projection: out = g_att @ Wo + bo (f32 out)
__global__ __launch_bounds__(256, 2) void proj_kernel(
    const float* __restrict__ bo, float* __restrict__ C)
{
    __shared__ unsigned As[GBM * AST];
    __shared__ unsigned Bs[GBK * BST];

    const int tid = threadIdx.x, lane = tid & 31, warp = tid >> 5;
    const int wm = warp >> 2, wn = warp & 3;
    const int r = lane >> 2, kq = lane & 3;
    const int bm = blockIdx.x * GBM;
    const int bn = blockIdx.y * GBN;

    float acc[4][4][4];
    #pragma unroll
    for (int mi = 0; mi < 4; mi++)
        #pragma unroll
        for (int ni = 0; ni < 4; ni++)
            #pragma unroll
            for (int c = 0; c < 4; c++) acc[mi][ni][c] = 0.f;

    for (int k0 = 0; k0 < QDIM; k0 += GBK) {
        load_tiles(As, Bs, g_att, wo_tf, bm, bn, k0, tid);
        __syncthreads();
        gemm_tile(As, Bs, wm, wn, r, kq, acc);
        __syncthreads();
    }

    #pragma unroll
    for (int mi = 0; mi < 4; mi++) {
        #pragma unroll
        for (int ni = 0; ni < 4; ni++) {
            int m0 = bm + wm * 64 + mi * 16 + r;
            int d  = wn * 32 + ni * 8 + 2 * kq;
            float bx = bo[bn + d], by = bo[bn + d + 1];
            *reinterpret_cast<float2*>(&C[(size_t)m0 * QDIM + bn + d]) =
                make_float2(acc[mi][ni][0] + bx, acc[mi][ni][1] + by);
            *reinterpret_cast<float2*>(&C[(size_t)(m0 + 8) * QDIM + bn + d]) =
                make_float2(acc[mi][ni][2] + bx, acc[mi][ni][3] + by);
        }
    }
}

// ---------------------------------------------------------------------------
// Flash attention: CTA = 128 q rows x (b,h); 8 warps, warp = 16 rows x 64 cols.
// Register online softmax (quad shuffles). P in per-warp private smem (tf32).
// ---------------------------------------------------------------------------
#define ATW 72
#define ATTN_SMEM ((128*ATW + 64*ATW + 64*ATW + 8*16*ATW) * 4 + 64 * 4)

__global__ __launch_bounds__(256, 2) void attn_kernel(const int* __restrict__ mask)
{
    extern __shared__ unsigned sm[];
    unsigned* Qs = sm;                       // [128][72] interleaved dh
    unsigned* Ks = Qs + 128 * ATW;           // [64][72] interleaved dh
    unsigned* Vs = Ks + 64 * ATW;            // [64][72] natural [key][d]
    unsigned* Pw = Vs + 64 * ATW;            // 8 x [16][72] interleaved key
    float* mskf  = (float*)(Pw + 8 * 16 * ATW);  // [64]

    const int tid = threadIdx.x, lane = tid & 31, warp = tid >> 5;
    const int r = lane >> 2, kq = lane & 3;
    const int qb = blockIdx.x, h = blockIdx.y, b = blockIdx.z;
    const size_t bh = (size_t)(b * HEADS + h) * SEQ;

    // load Q tile (pre-scaled tf32), interleaved
    const unsigned* qg = &g_q[(bh + qb * 128) * DHEAD];
    #pragma unroll
    for (int l = 0; l < 8; l++) {
        int lin = tid + l * 256;
        int row = lin >> 4, kg = lin & 15;
        uint4 v = *reinterpret_cast<const uint4*>(&qg[row * DHEAD + kg * 4]);
        unsigned* d = &Qs[row * ATW + (kg >> 1) * 8 + (kg & 1)];
        d[0] = v.x; d[2] = v.y; d[4] = v.z; d[6] = v.w;
    }

    float oacc[8][4];
    #pragma unroll
    for (int ni = 0; ni < 8; ni++)
        #pragma unroll
        for (int c = 0; c < 4; c++) oacc[ni][c] = 0.f;
    float m0 = -1e30f, m1 = -1e30f, l0 = 0.f, l1 = 0.f;

    unsigned* Pme = Pw + warp * 16 * ATW;
    const int row0 = warp * 16 + r;
    const int se0 = ((2 * kq) & 3) * 2 + ((2 * kq) >> 2);   // slot of col 2kq

    for (int kb = 0; kb < SEQ / 64; kb++) {
        __syncthreads();
        const unsigned* kgp = &g_k[(bh + kb * 64) * DHEAD];
        const unsigned* vgp = &g_v[(bh + kb * 64) * DHEAD];
        #pragma unroll
        for (int l = 0; l < 4; l++) {
            int lin = tid + l * 256;
            int row = lin >> 4, kg = lin & 15;
            uint4 kv = *reinterpret_cast<const uint4*>(&kgp[row * DHEAD + kg * 4]);
            unsigned* d = &Ks[row * ATW + (kg >> 1) * 8 + (kg & 1)];
            d[0] = kv.x; d[2] = kv.y; d[4] = kv.z; d[6] = kv.w;
            uint4 vv = *reinterpret_cast<const uint4*>(&vgp[row * DHEAD + kg * 4]);
            *reinterpret_cast<uint4*>(&Vs[row * ATW + kg * 4]) = vv;
        }
        if (tid < 64) mskf[tid] = (mask[b * SEQ + kb * 64 + tid] == 0) ? -1e30f : 0.f;
        __syncthreads();

        // ---- S = Q K^T ----
        float sacc[8][4];
        #pragma unroll
        for (int ni = 0; ni < 8; ni++)
            #pragma unroll
            for (int c = 0; c < 4; c++) sacc[ni][c] = 0.f;

        #pragma unroll
        for (int s = 0; s < 8; s++) {
            uint2 qlo = *reinterpret_cast<const uint2*>(&Qs[row0 * ATW + s * 8 + 2 * kq]);
            uint2 qhi = *reinterpret_cast<const uint2*>(&Qs[(row0 + 8) * ATW + s * 8 + 2 * kq]);
            unsigned af[4] = {qlo.x, qhi.x, qlo.y, qhi.y};
            #pragma unroll
            for (int ni = 0; ni < 8; ni++) {
                uint2 kf = *reinterpret_cast<const uint2*>(&Ks[(ni * 8 + r) * ATW + s * 8 + 2 * kq]);
                unsigned bf[2] = {kf.x, kf.y};
                mma8(sacc[ni], af, bf);
            }
        }

        // ---- mask + register online softmax (rows r and r+8) ----
        float rx0 = -1e30f, rx1 = -1e30f;
        #pragma unroll
        for (int ni = 0; ni < 8; ni++) {
            float2 mb = *reinterpret_cast<const float2*>(&mskf[ni * 8 + 2 * kq]);
            sacc[ni][0] += mb.x; sacc[ni][1] += mb.y;
            sacc[ni][2] += mb.x; sacc[ni][3] += mb.y;
            rx0 = fmaxf(rx0, fmaxf(sacc[ni][0], sacc[ni][1]));
            rx1 = fmaxf(rx1, fmaxf(sacc[ni][2], sacc[ni][3]));
        }
        rx0 = fmaxf(rx0, __shfl_xor_sync(0xffffffffu, rx0, 1));
        rx0 = fmaxf(rx0, __shfl_xor_sync(0xffffffffu, rx0, 2));
        rx1 = fmaxf(rx1, __shfl_xor_sync(0xffffffffu, rx1, 1));
        rx1 = fmaxf(rx1, __shfl_xor_sync(0xffffffffu, rx1, 2));

        float mn0 = fmaxf(m0, rx0), mn1 = fmaxf(m1, rx1);
        float a0 = __expf(m0 - mn0), a1 = __expf(m1 - mn1);
        float rs0 = 0.f, rs1 = 0.f;
        #pragma unroll
        for (int ni = 0; ni < 8; ni++) {
            float p00 = __expf(sacc[ni][0] - mn0);
            float p01 = __expf(sacc[ni][1] - mn0);
            float p10 = __expf(sacc[ni][2] - mn1);
            float p11 = __expf(sacc[ni][3] - mn1);
            rs0 += p00 + p01; rs1 += p10 + p11;
            Pme[r * ATW + ni * 8 + se0]           = f2tf(p00);
            Pme[r * ATW + ni * 8 + se0 + 2]       = f2tf(p01);
            Pme[(r + 8) * ATW + ni * 8 + se0]     = f2tf(p10);
            Pme[(r + 8) * ATW + ni * 8 + se0 + 2] = f2tf(p11);
        }
        rs0 += __shfl_xor_sync(0xffffffffu, rs0, 1);
        rs0 += __shfl_xor_sync(0xffffffffu, rs0, 2);
        rs1 += __shfl_xor_sync(0xffffffffu, rs1, 1);
        rs1 += __shfl_xor_sync(0xffffffffu, rs1, 2);

        l0 = l0 * a0 + rs0; l1 = l1 * a1 + rs1;
        m0 = mn0; m1 = mn1;
        #pragma unroll
        for (int ni = 0; ni < 8; ni++) {
            oacc[ni][0] *= a0; oacc[ni][1] *= a0;
            oacc[ni][2] *= a1; oacc[ni][3] *= a1;
        }
        __syncwarp();

        // ---- O += P V ----
        #pragma unroll
        for (int s = 0; s < 8; s++) {
            uint2 plo = *reinterpret_cast<const uint2*>(&Pme[r * ATW + s * 8 + 2 * kq]);
            uint2 phi = *reinterpret_cast<const uint2*>(&Pme[(r + 8) * ATW + s * 8 + 2 * kq]);
            unsigned af[4] = {plo.x, phi.x, plo.y, phi.y};
            #pragma unroll
            for (int ni = 0; ni < 8; ni++) {
                unsigned bf[2];
                bf[0] = Vs[(s * 8 + kq) * ATW + ni * 8 + r];
                bf[1] = Vs[(s * 8 + kq + 4) * ATW + ni * 8 + r];
                mma8(oacc[ni], af, bf);
            }
        }
    }

    // epilogue -> g_att tf32 [B,T,H*dh]
    float i0 = 1.f / l0, i1 = 1.f / l1;
    int t0 = qb * 128 + warp * 16 + r;
    #pragma unroll
    for (int ni = 0; ni < 8; ni++) {
        int d = ni * 8 + 2 * kq;
        *reinterpret_cast<uint2*>(
            &g_att[((size_t)(b * SEQ + t0) * QDIM) + h * DHEAD + d]) =
            make_uint2(f2tf(oacc[ni][0] * i0), f2tf(oacc[ni][1] * i0));
        *reinterpret_cast<uint2*>(
            &g_att[((size_t)(b * SEQ + t0 + 8) * QDIM) + h * DHEAD + d]) =
            make_uint2(f2tf(oacc[ni][2] * i1), f2tf(oacc[ni][3] * i1));
    }
}

// ---------------------------------------------------------------------------
extern "C" void kernel_launch(void* const* d_in, const int* in_sizes, int n_in,
                              void* d_out, int out_size)
{
    const float* hidden = (const float*)d_in[0];
    const int*   amask  = (const int*)d_in[1];
    const float* Wq     = (const float*)d_in[2];
    const float* Wk     = (const float*)d_in[3];
    const float* Wv     = (const float*)d_in[4];
    const float* Wo     = (const float*)d_in[5];
    const float* bo     = (const float*)d_in[6];
    float* out          = (float*)d_out;

    cudaFuncSetAttribute(attn_kernel, cudaFuncAttributeMaxDynamicSharedMemorySize, ATTN_SMEM);

    cvt_kernel<<<(HID4 + 4 * W4 + 255) / 256, 256>>>(hidden, Wq, Wk, Wv, Wo);

    dim3 gq(MROWS / GBM, QDIM / GBN, 3);
    qkv_kernel<<<gq, 256>>>();

    dim3 ga(SEQ / 128, HEADS, BATCH);
    attn_kernel<<<ga, 256, ATTN_SMEM>>>(amask);

    dim3 gp(MROWS / GBM, QDIM / GBN);
    proj_kernel<<<gp, 256>>>(bo, out);
}